// round 12
// baseline (speedup 1.0000x reference)
#include <cuda_runtime.h>
#include <cuda_fp16.h>
#include <cstdint>

#define BATCH 64
#define T 512
#define C 384
#define H 64
#define BT (BATCH*T)

// Q, K projected fp16 row-major [row*H+col].
// V projected fp16 in PV-paired layout: per 64-row tile,
//   g_Vp[tile*2048 + k2*64 + col] = pack(V[2k2][col], V[2k2+1][col])
__device__ __half    g_Q[BT * H];
__device__ __half    g_K[BT * H];
__device__ uint32_t  g_Vp[BT * 32];
// Weights pre-packed fp16 half2 pairs along k: [mat][k2][n].
__device__ uint32_t  g_W16[3 * 192 * 64];

__device__ __forceinline__ uint32_t pack_h2(float a, float b) {
    __half2 h = __floats2half2_rn(a, b);
    return *(uint32_t*)&h;
}

__device__ __forceinline__ void mma_f16(float c[4], const uint32_t a[4],
                                        uint32_t b0, uint32_t b1) {
    asm volatile(
        "mma.sync.aligned.m16n8k16.row.col.f32.f16.f16.f32 "
        "{%0,%1,%2,%3}, {%4,%5,%6,%7}, {%8,%9}, {%0,%1,%2,%3};\n"
        : "+f"(c[0]), "+f"(c[1]), "+f"(c[2]), "+f"(c[3])
        : "r"(a[0]), "r"(a[1]), "r"(a[2]), "r"(a[3]), "r"(b0), "r"(b1));
}

// ---------------------------------------------------------------------------
// Kernel 0: pack W fp32 -> fp16 half2 pairs along k.
// ---------------------------------------------------------------------------
__global__ __launch_bounds__(256) void pack_w_kernel(
    const float* __restrict__ Wq,
    const float* __restrict__ Wk,
    const float* __restrict__ Wv)
{
    int idx = blockIdx.x * 256 + threadIdx.x;      // 144 blocks exactly
    int mat = idx / (192 * 64);
    int rem = idx - mat * (192 * 64);
    int k2 = rem >> 6;
    int n  = rem & 63;
    const float* W = (mat == 0) ? Wq : ((mat == 1) ? Wk : Wv);
    g_W16[idx] = pack_h2(W[(2 * k2) * H + n], W[(2 * k2 + 1) * H + n]);
}

// ---------------------------------------------------------------------------
// Kernel 1: fused QKV projection, fp16 m16n8k16, 512 threads = 16 warps
// as 8(M) x 2(N); warp tile 16 rows x 32 cols x 3 mats (A frags reused 3x).
// x read once chip-wide; x/W tiles double-buffered; 1 barrier/kt.
// Q,K stored row-major fp16; V stored PV-paired (shfl+byte_perm epilogue).
// Grid: BT/128 = 256 blocks.
// ---------------------------------------------------------------------------
#define AS2_STR 20
#define WT_STR 68

__global__ __launch_bounds__(512) void qkv_proj_kernel(const float* __restrict__ x)
{
    __shared__ uint32_t As2[2][128][AS2_STR];      // x tile fp16 pairs [m][k2]
    __shared__ uint32_t Wt[2][3][16][WT_STR];      // W tiles [mat][k2][n]

    const int tid  = threadIdx.x;
    const int lane = tid & 31;
    const int wid  = tid >> 5;
    const int warpM = wid & 7;      // 0..7 -> 16-row group
    const int warpN = wid >> 3;     // 0..1 -> 32-col group
    const int g  = lane >> 2;
    const int tg = lane & 3;
    const int row0 = blockIdx.x * 128;

    float c[3][4][4];
    #pragma unroll
    for (int mat = 0; mat < 3; ++mat)
        #pragma unroll
        for (int nf = 0; nf < 4; ++nf)
            #pragma unroll
            for (int j = 0; j < 4; ++j) c[mat][nf][j] = 0.0f;

    // initial tiles (kt=0) into buf 0
    #pragma unroll
    for (int i = 0; i < 2; ++i) {
        int s = tid + i * 512;
        int r = s >> 3;
        int c4 = (s & 7) * 4;
        float4 v = *(const float4*)&x[(row0 + r) * C + c4];
        *(uint2*)&As2[0][r][c4 >> 1] = make_uint2(pack_h2(v.x, v.y), pack_h2(v.z, v.w));
    }
    for (int s = tid; s < 768; s += 512) {
        int mat = s >> 8, k2 = (s >> 4) & 15, n4 = (s & 15) * 4;
        *(uint4*)&Wt[0][mat][k2][n4] =
            *(const uint4*)&g_W16[mat * (192 * 64) + k2 * 64 + n4];
    }

    for (int kt = 0; kt < 12; ++kt) {
        const int buf = kt & 1;
        __syncthreads();

        float4 xv[2];
        uint4 wv[2];
        const bool pf = (kt < 11);
        const bool w2 = (tid < 256);   // second W task
        if (pf) {
            #pragma unroll
            for (int i = 0; i < 2; ++i) {
                int s = tid + i * 512;
                int r = s >> 3;
                int c4 = (s & 7) * 4;
                xv[i] = *(const float4*)&x[(row0 + r) * C + (kt + 1) * 32 + c4];
            }
            {
                int s = tid;
                int mat = s >> 8, k2 = (s >> 4) & 15, n4 = (s & 15) * 4;
                wv[0] = *(const uint4*)&g_W16[mat * (192 * 64) + ((kt + 1) * 16 + k2) * 64 + n4];
            }
            if (w2) {
                int s = tid + 512;
                int mat = s >> 8, k2 = (s >> 4) & 15, n4 = (s & 15) * 4;
                wv[1] = *(const uint4*)&g_W16[mat * (192 * 64) + ((kt + 1) * 16 + k2) * 64 + n4];
            }
        }

        #pragma unroll
        for (int ks = 0; ks < 2; ++ks) {
            const int p = ks * 8 + tg;
            uint32_t a[4];
            {
                int r = warpM * 16 + g;
                a[0] = As2[buf][r][p];
                a[1] = As2[buf][r + 8][p];
                a[2] = As2[buf][r][p + 4];
                a[3] = As2[buf][r + 8][p + 4];
            }
            #pragma unroll
            for (int mat = 0; mat < 3; ++mat) {
                #pragma unroll
                for (int nf = 0; nf < 4; ++nf) {
                    int n = warpN * 32 + nf * 8 + g;
                    uint32_t b0 = Wt[buf][mat][p][n];
                    uint32_t b1 = Wt[buf][mat][p + 4][n];
                    mma_f16(c[mat][nf], a, b0, b1);
                }
            }
        }

        if (pf) {
            #pragma unroll
            for (int i = 0; i < 2; ++i) {
                int s = tid + i * 512;
                int r = s >> 3;
                int c4 = (s & 7) * 4;
                *(uint2*)&As2[buf ^ 1][r][c4 >> 1] =
                    make_uint2(pack_h2(xv[i].x, xv[i].y), pack_h2(xv[i].z, xv[i].w));
            }
            {
                int s = tid;
                int mat = s >> 8, k2 = (s >> 4) & 15, n4 = (s & 15) * 4;
                *(uint4*)&Wt[buf ^ 1][mat][k2][n4] = wv[0];
            }
            if (w2) {
                int s = tid + 512;
                int mat = s >> 8, k2 = (s >> 4) & 15, n4 = (s & 15) * 4;
                *(uint4*)&Wt[buf ^ 1][mat][k2][n4] = wv[1];
            }
        }
    }

    const int r = row0 + warpM * 16 + g;

    // Q, K: row-major fp16
    #pragma unroll
    for (int mat = 0; mat < 2; ++mat) {
        __half* O = (mat == 0) ? g_Q : g_K;
        #pragma unroll
        for (int nf = 0; nf < 4; ++nf) {
            int col = warpN * 32 + nf * 8 + 2 * tg;
            *(uint32_t*)&O[r * H + col]       = pack_h2(c[mat][nf][0], c[mat][nf][1]);
            *(uint32_t*)&O[(r + 8) * H + col] = pack_h2(c[mat][nf][2], c[mat][nf][3]);
        }
    }

    // V: PV-paired layout. Row r's pair-partner is r^1 (lane xor 4).
    #pragma unroll
    for (int nf = 0; nf < 4; ++nf) {
        int col = warpN * 32 + nf * 8 + 2 * tg;
        uint32_t my01 = pack_h2(c[2][nf][0], c[2][nf][1]);   // row r,   cols (col, col+1)
        uint32_t my23 = pack_h2(c[2][nf][2], c[2][nf][3]);   // row r+8
        uint32_t pr01 = __shfl_xor_sync(0xffffffffu, my01, 4);
        uint32_t pr23 = __shfl_xor_sync(0xffffffffu, my23, 4);
        if (!(g & 1)) {   // even row: owns pairs (r, r+1) and (r+8, r+9)
            uint32_t w0 = __byte_perm(my01, pr01, 0x5410);   // (V[r][col],   V[r+1][col])
            uint32_t w1 = __byte_perm(my01, pr01, 0x7632);   // (V[r][col+1], V[r+1][col+1])
            uint32_t w2 = __byte_perm(my23, pr23, 0x5410);
            uint32_t w3 = __byte_perm(my23, pr23, 0x7632);
            int idx0 = (r >> 6) * 2048 + ((r & 63) >> 1) * 64 + col;
            int r8 = r + 8;
            int idx1 = (r8 >> 6) * 2048 + ((r8 & 63) >> 1) * 64 + col;
            *(uint2*)&g_Vp[idx0] = make_uint2(w0, w1);
            *(uint2*)&g_Vp[idx1] = make_uint2(w2, w3);
        }
    }
}

// ---------------------------------------------------------------------------
// Kernel 2: causal flash attention, 128 q-rows per block (8 warps, 256 thr),
// double-buffered K/V (V loads are straight copies from paired layout),
// P in registers, one barrier per tile. 256 blocks, balanced pairing.
// ---------------------------------------------------------------------------
#define Q2_STR 36
#define K2_STR 36
#define V2_STR 72
#define ATTN_SMEM_U32 (128 * Q2_STR + 2 * 64 * K2_STR + 2 * 32 * V2_STR)
#define ATTN_SMEM_BYTES (ATTN_SMEM_U32 * 4)

__global__ __launch_bounds__(256) void attn_kernel(float* __restrict__ out)
{
    extern __shared__ uint32_t sm_at[];
    uint32_t* Qs2 = sm_at;                               // [128][36]
    uint32_t (*K2)[64 * K2_STR] =
        (uint32_t (*)[64 * K2_STR])(sm_at + 128 * Q2_STR);
    uint32_t (*V2)[32 * V2_STR] =
        (uint32_t (*)[32 * V2_STR])(sm_at + 128 * Q2_STR + 2 * 64 * K2_STR);

    const int tid  = threadIdx.x;
    const int lane = tid & 31;
    const int wid  = tid >> 5;
    const int g    = lane >> 2;
    const int tg   = lane & 3;

    // balanced (b, qb) assignment
    int bid = blockIdx.x;
    int b, qb;
    if (bid < 148) { qb = bid & 3; b = bid >> 2; }
    else { int s = bid - 148; qb = 3 - (s & 3); b = 37 + (s >> 2); }

    const int tmax = 2 * qb + 1;
    const float scale = 0.125f;

    // ---- Q tile ----
    {
        const uint4* qsrc = (const uint4*)(g_Q + (b * T + qb * 128) * H);
        #pragma unroll
        for (int i = 0; i < 4; ++i) {
            int s = tid + i * 256;
            int r = s >> 3;
            int c4 = (s & 7) * 4;
            *(uint4*)&Qs2[r * Q2_STR + c4] = qsrc[s];
        }
    }
    // ---- K/V tile 0 into buf 0 ----
    {
        const uint4* ksrc = (const uint4*)(g_K + (b * T) * H);
        #pragma unroll
        for (int i = 0; i < 2; ++i) {
            int s = tid + i * 256;
            *(uint4*)&K2[0][(s >> 3) * K2_STR + (s & 7) * 4] = ksrc[s];
        }
        {
            const uint4* vsrc = (const uint4*)(g_Vp + (b * 8) * 2048);
            uint32_t* dst = &V2[0][(tid >> 3) * V2_STR + (tid & 7) * 8];
            *(uint4*)&dst[0] = vsrc[tid * 2];
            *(uint4*)&dst[4] = vsrc[tid * 2 + 1];
        }
    }
    __syncthreads();

    // ---- Q fragments (register resident) ----
    uint32_t qa[4][4];
    const int qrow = wid * 16 + g;
    #pragma unroll
    for (int ks = 0; ks < 4; ++ks) {
        int p = ks * 8 + tg;
        qa[ks][0] = Qs2[qrow * Q2_STR + p];
        qa[ks][1] = Qs2[(qrow + 8) * Q2_STR + p];
        qa[ks][2] = Qs2[qrow * Q2_STR + p + 4];
        qa[ks][3] = Qs2[(qrow + 8) * Q2_STR + p + 4];
    }

    float m[2] = {-1e30f, -1e30f};
    float l[2] = {0.0f, 0.0f};
    float o[8][4];
    #pragma unroll
    for (int nf = 0; nf < 8; ++nf)
        #pragma unroll
        for (int j = 0; j < 4; ++j) o[nf][j] = 0.0f;

    const int rowg0 = qb * 128 + wid * 16 + g;

    for (int t = 0; t <= tmax; ++t) {
        const int buf = t & 1;
        const bool pf = (t < tmax);

        uint4 kp[2], vp[2];
        if (pf) {
            const uint4* ksrc = (const uint4*)(g_K + (b * T + (t + 1) * 64) * H);
            #pragma unroll
            for (int i = 0; i < 2; ++i) kp[i] = ksrc[tid + i * 256];
            const uint4* vsrc = (const uint4*)(g_Vp + (b * 8 + t + 1) * 2048);
            vp[0] = vsrc[tid * 2];
            vp[1] = vsrc[tid * 2 + 1];
        }

        // --- S = Q K^T ---
        float sf[8][4];
        #pragma unroll
        for (int nf = 0; nf < 8; ++nf)
            #pragma unroll
            for (int j = 0; j < 4; ++j) sf[nf][j] = 0.0f;

        #pragma unroll
        for (int ks = 0; ks < 4; ++ks) {
            const int p = ks * 8 + tg;
            #pragma unroll
            for (int nf = 0; nf < 8; ++nf) {
                int key = nf * 8 + g;
                mma_f16(sf[nf], qa[ks],
                        K2[buf][key * K2_STR + p], K2[buf][key * K2_STR + p + 4]);
            }
        }

        if (pf) {
            #pragma unroll
            for (int i = 0; i < 2; ++i) {
                int s = tid + i * 256;
                *(uint4*)&K2[buf ^ 1][(s >> 3) * K2_STR + (s & 7) * 4] = kp[i];
            }
            {
                uint32_t* dst = &V2[buf ^ 1][(tid >> 3) * V2_STR + (tid & 7) * 8];
                *(uint4*)&dst[0] = vp[0];
                *(uint4*)&dst[4] = vp[1];
            }
        }

        // --- online softmax ---
        const bool maskit = (t >= 2 * qb);
        float mnew[2] = {m[0], m[1]};
        #pragma unroll
        for (int nf = 0; nf < 8; ++nf)
            #pragma unroll
            for (int j = 0; j < 4; ++j) {
                int rr = j >> 1;
                float v = sf[nf][j] * scale;
                if (maskit) {
                    int col = t * 64 + nf * 8 + 2 * tg + (j & 1);
                    int row = rowg0 + rr * 8;
                    if (col > row) v = -1e30f;
                }
                sf[nf][j] = v;
                mnew[rr] = fmaxf(mnew[rr], v);
            }
        #pragma unroll
        for (int rr = 0; rr < 2; ++rr) {
            mnew[rr] = fmaxf(mnew[rr], __shfl_xor_sync(0xffffffffu, mnew[rr], 1));
            mnew[rr] = fmaxf(mnew[rr], __shfl_xor_sync(0xffffffffu, mnew[rr], 2));
        }
        float alpha[2];
        #pragma unroll
        for (int rr = 0; rr < 2; ++rr) {
            alpha[rr] = __expf(m[rr] - mnew[rr]);
            m[rr] = mnew[rr];
        }
        float ls[2] = {0.0f, 0.0f};
        #pragma unroll
        for (int nf = 0; nf < 8; ++nf)
            #pragma unroll
            for (int j = 0; j < 4; ++j) {
                int rr = j >> 1;
                float pexp = __expf(sf[nf][j] - m[rr]);
                sf[nf][j] = pexp;
                ls[rr] += pexp;
            }
        #pragma unroll
        for (int rr = 0; rr < 2; ++rr) {
            ls[rr] += __shfl_xor_sync(0xffffffffu, ls[rr], 1);
            ls[rr] += __shfl_xor_sync(0xffffffffu, ls[rr], 2);
            l[rr] = l[rr] * alpha[rr] + ls[rr];
        }
        #pragma unroll
        for (int nf = 0; nf < 8; ++nf) {
            o[nf][0] *= alpha[0];
            o[nf][1] *= alpha[0];
            o[nf][2] *= alpha[1];
            o[nf][3] *= alpha[1];
        }

        // --- O += P V : P fragments built in registers ---
        #pragma unroll
        for (int ks = 0; ks < 4; ++ks) {
            uint32_t pa[4];
            pa[0] = pack_h2(sf[2 * ks][0],     sf[2 * ks][1]);
            pa[1] = pack_h2(sf[2 * ks][2],     sf[2 * ks][3]);
            pa[2] = pack_h2(sf[2 * ks + 1][0], sf[2 * ks + 1][1]);
            pa[3] = pack_h2(sf[2 * ks + 1][2], sf[2 * ks + 1][3]);
            #pragma unroll
            for (int nf = 0; nf < 8; ++nf) {
                int hh = nf * 8 + g;
                mma_f16(o[nf], pa,
                        V2[buf][(ks * 8 + tg) * V2_STR + hh],
                        V2[buf][(ks * 8 + tg + 4) * V2_STR + hh]);
            }
        }

        __syncthreads();
    }

    const float inv0 = 1.0f / l[0];
    const float inv1 = 1.0f / l[1];
    const int grow = b * T + qb * 128 + wid * 16 + g;
    #pragma unroll
    for (int nf = 0; nf < 8; ++nf) {
        int col = nf * 8 + 2 * tg;
        *(float2*)&out[grow * H + col] =
            make_float2(o[nf][0] * inv0, o[nf][1] * inv0);
        *(float2*)&out[(grow + 8) * H + col] =
            make_float2(o[nf][2] * inv1, o[nf][3] * inv1);
    }
}

// ---------------------------------------------------------------------------
extern "C" void kernel_launch(void* const* d_in, const int* in_sizes, int n_in,
                              void* d_out, int out_size)
{
    const float* x  = (const float*)d_in[0];
    const float* Wq = (const float*)d_in[1];
    const float* Wk = (const float*)d_in[2];
    const float* Wv = (const float*)d_in[3];
    float* out = (float*)d_out;

    pack_w_kernel<<<144, 256>>>(Wq, Wk, Wv);

    qkv_proj_kernel<<<BT / 128, 512>>>(x);

    cudaFuncSetAttribute(attn_kernel,
                         cudaFuncAttributeMaxDynamicSharedMemorySize,
                         ATTN_SMEM_BYTES);
    attn_kernel<<<256, 256, ATTN_SMEM_BYTES>>>(out);
}